// round 14
// baseline (speedup 1.0000x reference)
#include <cuda_runtime.h>
#include <math.h>

#define Nn 19
#define PADA 21      // eig kernel pad (conflict-free: gcd(21,32)=1)
#define PADG 20      // Gt row pad in dense (5 float4 per row)
#define ZPAD 68      // Z row stride: 16B-aligned, 3-way max LN conflicts
#define PADW 84      // W stage pad: 16B-aligned rows, conflict-free LDS.128
#define KE 16
#define Dd 64
#define Tt 1024
#define Bb 16
#define Gg (Bb*Tt)   // 16384 graphs
#define SWEEP_BASE 4 // always run 4 sweeps...
#define SWEEP_MAX  7 // ...then up to 3 more while off-diag^2 >= OFF_TOL
#define OFF_TOL 1e-9f
#define ALPHA_C 0.05f
#define HOPC 0.475f  // (1-alpha)/K
#define LN_EPS 1e-5f

// scratch (allocation-free rule: __device__ globals)
__device__ float g_G[(size_t)Gg*Nn*Nn];       // fused propagation operator G^T
__device__ float g_pe[(size_t)Gg*Nn*KE];      // ~19.9 MB

__device__ __forceinline__ float softplusf(float x){
    return fmaxf(x, 0.0f) + log1pf(expf(-fabsf(x)));
}

// ---------------------------------------------------------------------------
// Kernel A: per-graph (one warp each): a_norm -> G (transposed, fused 2-hop)
// + symmetrized Laplacian + adaptive-sweep Jacobi + PE extraction.
// ---------------------------------------------------------------------------
__global__ void __launch_bounds__(256) eig_kernel(
    const float* __restrict__ adjacency,
    const float* __restrict__ edge_w_p,
    const float* __restrict__ edge_b_p)
{
    __shared__ float smem[8*(2*Nn*PADA + 96)];
    const int w = threadIdx.x >> 5;
    const int l = threadIdx.x & 31;
    const int g = blockIdx.x*8 + w;

    float* M   = smem + w*(2*Nn*PADA + 96);   // adj -> identity -> EVEC
    float* V   = M + Nn*PADA;                 // w -> a_norm -> lapS -> diag
    float* AUX = V + Nn*PADA;
    float* CS  = AUX;                         // 9 cosines
    float* SS  = AUX + 9;                     // 9 sines
    float* DIS = AUX + 18;                    // 19
    int*   ORD = (int*)(AUX + 40);            // 16
    float* SGN = AUX + 56;                    // 16
    int*   PSi = (int*)(AUX + 72);            // 9 p-indices (per round)
    int*   QSi = (int*)(AUX + 81);            // 9 q-indices

    const float ew = edge_w_p[0];
    const float eb = edge_b_p[0];
    const float* adj = adjacency + (size_t)g*Nn*Nn;

    for (int i = l; i < Nn*Nn; i += 32)
        M[(i/Nn)*PADA + (i%Nn)] = adj[i];
    __syncwarp();

    for (int i = l; i < Nn*Nn; i += 32){
        int r = i/Nn, c = i%Nn;
        float a = M[r*PADA + c];
        V[r*PADA + c] = (a > 0.0f) ? softplusf(a*ew + eb) : 0.0f;
    }
    __syncwarp();
    if (l < Nn){
        if (!(M[l*PADA + l] > 0.0f)) V[l*PADA + l] += 1.0f;
    }
    __syncwarp();

    if (l < Nn){
        float dsum = 0.0f;
        #pragma unroll
        for (int i = 0; i < Nn; i++) dsum += V[i*PADA + l];
        DIS[l] = (dsum > 0.0f) ? rsqrtf(fmaxf(dsum, 1e-30f)) : 0.0f;
    }
    __syncwarp();

    // a_norm in place: V = dis_r * V * dis_c
    for (int i = l; i < Nn*Nn; i += 32){
        int r = i/Nn, c = i%Nn;
        V[r*PADA + c] = DIS[r]*V[r*PADA + c]*DIS[c];
    }
    __syncwarp();

    // G^T to global: Gt[n,i] = a*(i==n) + C*(A[i,n] + (A^2)[i,n])
    {
        float* gG = g_G + (size_t)g*Nn*Nn;
        for (int e = l; e < Nn*Nn; e += 32){
            int n = e/Nn, i = e - n*Nn;
            float s = 0.0f;
            #pragma unroll
            for (int j = 0; j < Nn; j++) s += V[i*PADA + j]*V[j*PADA + n];
            float val = HOPC*(V[i*PADA + n] + s);
            if (i == n) val += ALPHA_C;
            gG[e] = val;
        }
    }
    __syncwarp();

    // PE normalization: deg = max(row sums of raw adj, 1e-6)
    if (l < Nn){
        float dsum = 0.0f;
        #pragma unroll
        for (int j = 0; j < Nn; j++) dsum += M[l*PADA + j];
        DIS[l] = rsqrtf(fmaxf(dsum, 1e-6f));
    }
    __syncwarp();

    for (int i = l; i < Nn*Nn; i += 32){
        int r = i/Nn, c = i%Nn;
        float an = 0.5f * DIS[r]*DIS[c] * (M[r*PADA + c] + M[c*PADA + r]);
        V[r*PADA + c] = ((r == c) ? (1.0f + 1e-5f) : 0.0f) - an;
    }
    __syncwarp();

    for (int i = l; i < Nn*Nn; i += 32){
        int r = i/Nn, c = i%Nn;
        M[r*PADA + c] = (r == c) ? 1.0f : 0.0f;
    }
    __syncwarp();

    // per-lane round-invariant task descriptors (offsets, not pointers)
    int  cOff[11];   // (m? M : V) row base, relative to M
    int  cK[11];     // k-1
    bool cValid[11];
    #pragma unroll
    for (int it = 0; it < 11; ++it){
        int t0 = l + 32*it;
        cValid[it] = (t0 < 2*9*Nn);
        int tt = cValid[it] ? t0 : 0;
        int m = tt / (9*Nn);
        int u = tt % (9*Nn);
        cK[it]   = u / Nn;
        cOff[it] = (m ? 0 : Nn*PADA) + (u % Nn)*PADA;
    }
    int  rK[6], rJ[6];
    bool rValid[6];
    #pragma unroll
    for (int it = 0; it < 6; ++it){
        int t0 = l + 32*it;
        rValid[it] = (t0 < 9*Nn);
        int tt = rValid[it] ? t0 : 0;
        rK[it] = tt / Nn;
        rJ[it] = tt % Nn;
    }

    for (int sweep = 0; sweep < SWEEP_MAX; ++sweep){
        if (sweep >= SWEEP_BASE){
            // off-diagonal Frobenius^2; skip remaining sweeps if converged
            float off = 0.0f;
            for (int e = l; e < Nn*Nn; e += 32){
                int rr = e/Nn, cc = e - rr*Nn;
                float v = V[rr*PADA + cc];
                if (rr != cc) off += v*v;
            }
            #pragma unroll
            for (int o = 16; o; o >>= 1)
                off += __shfl_xor_sync(0xffffffffu, off, o);
            if (off < OFF_TOL) break;
        }
        for (int r = 0; r < Nn; r++){
            if (l >= 1 && l <= 9){
                int k = l;
                int p = r + k; if (p >= Nn) p -= Nn;
                int q = r - k; if (q < 0)  q += Nn;
                float app = V[p*PADA + p];
                float aqq = V[q*PADA + q];
                float apq = V[p*PADA + q];
                float c = 1.0f, s = 0.0f;
                if (fabsf(apq) > 1e-30f){
                    float tau = (aqq - app) / (2.0f*apq);
                    float t = 1.0f / (fabsf(tau) + sqrtf(1.0f + tau*tau));
                    if (tau < 0.0f) t = -t;
                    c = rsqrtf(1.0f + t*t);
                    s = t*c;
                }
                CS[k-1] = c; SS[k-1] = s;
                PSi[k-1] = p; QSi[k-1] = q;
            }
            __syncwarp();
            #pragma unroll
            for (int it = 0; it < 11; ++it){
                if (cValid[it]){
                    int k = cK[it];
                    int p = PSi[k], q = QSi[k];
                    float c = CS[k], s = SS[k];
                    float* base = M + cOff[it];
                    float vp = base[p];
                    float vq = base[q];
                    base[p] = c*vp - s*vq;
                    base[q] = s*vp + c*vq;
                }
            }
            __syncwarp();
            #pragma unroll
            for (int it = 0; it < 6; ++it){
                if (rValid[it]){
                    int k = rK[it], j = rJ[it];
                    int p = PSi[k], q = QSi[k];
                    float c = CS[k], s = SS[k];
                    float vp = V[p*PADA + j];
                    float vq = V[q*PADA + j];
                    V[p*PADA + j] = c*vp - s*vq;
                    V[q*PADA + j] = s*vp + c*vq;
                }
            }
            __syncwarp();
        }
    }

    if (l < Nn){
        float dv = V[l*PADA + l];
        int rank = 0;
        #pragma unroll
        for (int j = 0; j < Nn; j++){
            float dj = V[j*PADA + j];
            rank += (dj < dv) || (dj == dv && j < l);
        }
        if (rank < KE) ORD[rank] = l;
    }
    __syncwarp();
    if (l < KE){
        int i = ORD[l];
        float sum = 0.0f;
        #pragma unroll
        for (int n = 0; n < Nn; n++) sum += M[n*PADA + i];
        SGN[l] = (sum > 0.0f) ? 1.0f : ((sum < 0.0f) ? -1.0f : 1.0f);
    }
    __syncwarp();
    {
        float* gp = g_pe + (size_t)g*Nn*KE;
        for (int t0 = l; t0 < Nn*KE; t0 += 32){
            int n = t0 / KE, m = t0 % KE;
            float v = M[n*PADA + ORD[m]] * SGN[m];
            if (isnan(v)) v = 0.0f;
            else if (isinf(v)) v = (v > 0.0f) ? 1.0f : -1.0f;
            gp[t0] = v;
        }
    }
}

// ---------------------------------------------------------------------------
// Kernel B: CTA-per-graph fused SSGConv0 -> LN0 -> SSGConv1 + res -> LN1.
// Weights staged in shared; wreg filled in 2 passes (unroll 1) to cap
// register pressure; acc[10] compile-time indexed (half1 uses dummy row 19).
// __launch_bounds__(128,5) pins 5 CTAs/SM.
// ---------------------------------------------------------------------------
__global__ void __launch_bounds__(128, 5) dense_kernel(
    const float* __restrict__ features,
    const float* __restrict__ W0, const float* __restrict__ b0,
    const float* __restrict__ W1, const float* __restrict__ b1,
    const float* __restrict__ ln0g, const float* __restrict__ ln0b,
    const float* __restrict__ ln1g, const float* __restrict__ ln1b,
    float* __restrict__ out)
{
    __shared__ __align__(16) float Gt[20*PADG];   // 20 rows (row 19 zeroed)
    __shared__ __align__(16) float XC[20*80];     // x|pe; reused as h1 (20xZPAD)
    __shared__ __align__(16) float Z0[20*ZPAD];
    __shared__ __align__(16) float Z1[20*ZPAD];
    __shared__ __align__(16) float SW[64*PADW];   // staged weights (W0, then W1)
    __shared__ float MU[20], RS[20];

    const int g = blockIdx.x;
    const int b = g >> 10;
    const int t = g & 1023;
    const int tid = threadIdx.x;

    // load G^T (zero pad col and dummy row 19)
    {
        const float* gG = g_G + (size_t)g*Nn*Nn;
        for (int e = tid; e < Nn*Nn; e += 128)
            Gt[(e/Nn)*PADG + (e%Nn)] = gG[e];
        if (tid < 20) Gt[tid*PADG + Nn] = 0.0f;
        if (tid < PADG) Gt[Nn*PADG + tid] = 0.0f;
    }
    // stage W0 (64x80) coalesced into SW rows of stride 84
    for (int i = tid; i < 64*80; i += 128){
        int r = i / 80, c = i - r*80;
        SW[r*PADW + c] = W0[i];
    }
    // load x: XC[n][0:64] = features[b, n, t, :]
    for (int i = tid; i < Nn*64; i += 128){
        int n = i >> 6, dd = i & 63;
        XC[n*80 + dd] = features[((size_t)((b*Nn + n)*Tt + t))*64 + dd];
    }
    // load pe: XC[n][64:80]
    {
        const float* gp = g_pe + (size_t)g*Nn*KE;
        for (int i = tid; i < Nn*KE; i += 128){
            int n = i / KE, m = i % KE;
            XC[n*80 + 64 + m] = gp[i];
        }
    }
    __syncthreads();

    const int d    = tid & 63;
    const int half = tid >> 6;
    const int nb   = half*10;     // nodes nb..nb+9 (row 19 is scratch)

    // ---- GEMM0: Z0 = XC @ W0^T  (2 passes of 40 cols; wreg from smem) ----
    {
        float acc[10];
        #pragma unroll
        for (int m = 0; m < 10; m++) acc[m] = 0.0f;
        #pragma unroll 1
        for (int pass = 0; pass < 2; ++pass){
            float wreg[40];
            #pragma unroll
            for (int j4 = 0; j4 < 10; j4++){
                float4 v = *reinterpret_cast<const float4*>(SW + d*PADW + pass*40 + j4*4);
                wreg[j4*4+0] = v.x; wreg[j4*4+1] = v.y;
                wreg[j4*4+2] = v.z; wreg[j4*4+3] = v.w;
            }
            #pragma unroll
            for (int m = 0; m < 10; m++){
                const float4* xr = reinterpret_cast<const float4*>(XC + (nb+m)*80 + pass*40);
                float a = 0.0f;
                #pragma unroll
                for (int f4 = 0; f4 < 10; f4++){
                    float4 x = xr[f4];
                    a += x.x*wreg[f4*4+0] + x.y*wreg[f4*4+1]
                       + x.z*wreg[f4*4+2] + x.w*wreg[f4*4+3];
                }
                acc[m] += a;
            }
        }
        #pragma unroll
        for (int m = 0; m < 10; m++) Z0[(nb+m)*ZPAD + d] = acc[m];
    }
    __syncthreads();

    // stage W1 (64x64) into SW (overwrites W0; consumers re-read after LN0 sync)
    for (int i = tid; i < 64*64; i += 128){
        int r = i >> 6, c = i & 63;
        SW[r*PADW + c] = W1[i];
    }

    // ---- prop0: Z1 = G^T Z0 + b0 ----
    {
        float zc[20];
        #pragma unroll
        for (int i = 0; i < Nn; i++) zc[i] = Z0[i*ZPAD + d];
        zc[19] = 0.0f;
        float bb = b0[d];
        #pragma unroll
        for (int m = 0; m < 10; m++){
            int n = nb + m;
            const float4* gr = reinterpret_cast<const float4*>(Gt + n*PADG);
            float4 g0 = gr[0], g1 = gr[1], g2 = gr[2], g3 = gr[3], g4 = gr[4];
            float acc =
                g0.x*zc[0]  + g0.y*zc[1]  + g0.z*zc[2]  + g0.w*zc[3]
              + g1.x*zc[4]  + g1.y*zc[5]  + g1.z*zc[6]  + g1.w*zc[7]
              + g2.x*zc[8]  + g2.y*zc[9]  + g2.z*zc[10] + g2.w*zc[11]
              + g3.x*zc[12] + g3.y*zc[13] + g3.z*zc[14] + g3.w*zc[15]
              + g4.x*zc[16] + g4.y*zc[17] + g4.z*zc[18] + g4.w*zc[19];
            Z1[n*ZPAD + d] = acc + bb;
        }
    }
    __syncthreads();

    // ---- LN0 stats on Z1 (stride-68 -> 3-way conflicts max) ----
    if (tid < Nn){
        float mu = 0.0f;
        #pragma unroll
        for (int j = 0; j < 64; j++) mu += Z1[tid*ZPAD + j];
        mu *= (1.0f/64.0f);
        float var = 0.0f;
        #pragma unroll
        for (int j = 0; j < 64; j++){ float dv = Z1[tid*ZPAD + j] - mu; var += dv*dv; }
        var *= (1.0f/64.0f);
        MU[tid] = mu; RS[tid] = rsqrtf(var + LN_EPS);
    }
    if (tid == Nn){ MU[19] = 0.0f; RS[19] = 0.0f; }  // keep scratch row finite
    __syncthreads();
    // LN0 apply -> Z0 (GEMM1 input AND residual)
    {
        float gg = ln0g[d], bbb = ln0b[d];
        #pragma unroll
        for (int m = 0; m < 10; m++){
            int n = nb + m;
            Z0[n*ZPAD + d] = (Z1[n*ZPAD + d] - MU[n])*RS[n]*gg + bbb;
        }
    }
    __syncthreads();

    // ---- GEMM1: Z1 = Z0 @ W1^T  (2 passes of 32 cols) ----
    {
        float acc[10];
        #pragma unroll
        for (int m = 0; m < 10; m++) acc[m] = 0.0f;
        #pragma unroll 1
        for (int pass = 0; pass < 2; ++pass){
            float wreg[32];
            #pragma unroll
            for (int j4 = 0; j4 < 8; j4++){
                float4 v = *reinterpret_cast<const float4*>(SW + d*PADW + pass*32 + j4*4);
                wreg[j4*4+0] = v.x; wreg[j4*4+1] = v.y;
                wreg[j4*4+2] = v.z; wreg[j4*4+3] = v.w;
            }
            #pragma unroll
            for (int m = 0; m < 10; m++){
                const float4* xr = reinterpret_cast<const float4*>(Z0 + (nb+m)*ZPAD + pass*32);
                float a = 0.0f;
                #pragma unroll
                for (int f4 = 0; f4 < 8; f4++){
                    float4 x = xr[f4];
                    a += x.x*wreg[f4*4+0] + x.y*wreg[f4*4+1]
                       + x.z*wreg[f4*4+2] + x.w*wreg[f4*4+3];
                }
                acc[m] += a;
            }
        }
        #pragma unroll
        for (int m = 0; m < 10; m++) Z1[(nb+m)*ZPAD + d] = acc[m];
    }
    __syncthreads();

    // ---- prop1 + residual: h1 = G^T Z1 + b1 + Z0  -> XC (stride ZPAD) ----
    {
        float zc[20];
        #pragma unroll
        for (int i = 0; i < Nn; i++) zc[i] = Z1[i*ZPAD + d];
        zc[19] = 0.0f;
        float bb = b1[d];
        #pragma unroll
        for (int m = 0; m < 10; m++){
            int n = nb + m;
            const float4* gr = reinterpret_cast<const float4*>(Gt + n*PADG);
            float4 g0 = gr[0], g1 = gr[1], g2 = gr[2], g3 = gr[3], g4 = gr[4];
            float acc =
                g0.x*zc[0]  + g0.y*zc[1]  + g0.z*zc[2]  + g0.w*zc[3]
              + g1.x*zc[4]  + g1.y*zc[5]  + g1.z*zc[6]  + g1.w*zc[7]
              + g2.x*zc[8]  + g2.y*zc[9]  + g2.z*zc[10] + g2.w*zc[11]
              + g3.x*zc[12] + g3.y*zc[13] + g3.z*zc[14] + g3.w*zc[15]
              + g4.x*zc[16] + g4.y*zc[17] + g4.z*zc[18] + g4.w*zc[19];
            XC[n*ZPAD + d] = acc + bb + Z0[n*ZPAD + d];
        }
    }
    __syncthreads();

    // ---- LN1 stats on XC ----
    if (tid < Nn){
        float mu = 0.0f;
        #pragma unroll
        for (int j = 0; j < 64; j++) mu += XC[tid*ZPAD + j];
        mu *= (1.0f/64.0f);
        float var = 0.0f;
        #pragma unroll
        for (int j = 0; j < 64; j++){ float dv = XC[tid*ZPAD + j] - mu; var += dv*dv; }
        var *= (1.0f/64.0f);
        MU[tid] = mu; RS[tid] = rsqrtf(var + LN_EPS);
    }
    __syncthreads();
    {
        float gg = ln1g[d], bbb = ln1b[d];
        #pragma unroll
        for (int m = 0; m < 10; m++){
            int n = nb + m;
            if (n < Nn){
                float v = (XC[n*ZPAD + d] - MU[n])*RS[n]*gg + bbb;
                out[((size_t)((b*Nn + n)*Tt + t))*64 + d] = v;
            }
        }
    }
}

// ---------------------------------------------------------------------------
extern "C" void kernel_launch(void* const* d_in, const int* in_sizes, int n_in,
                              void* d_out, int out_size)
{
    const float* features  = (const float*)d_in[0];
    const float* adjacency = (const float*)d_in[1];
    const float* edge_w    = (const float*)d_in[2];
    const float* edge_b    = (const float*)d_in[3];
    const float* gnn0_W    = (const float*)d_in[4];
    const float* gnn0_b    = (const float*)d_in[5];
    const float* gnn1_W    = (const float*)d_in[6];
    const float* gnn1_b    = (const float*)d_in[7];
    const float* ln0_g     = (const float*)d_in[8];
    const float* ln0_b     = (const float*)d_in[9];
    const float* ln1_g     = (const float*)d_in[10];
    const float* ln1_b     = (const float*)d_in[11];
    float* out = (float*)d_out;

    eig_kernel<<<Gg/8, 256>>>(adjacency, edge_w, edge_b);
    dense_kernel<<<Gg, 128>>>(features, gnn0_W, gnn0_b, gnn1_W, gnn1_b,
                              ln0_g, ln0_b, ln1_g, ln1_b, out);
}

// round 15
// speedup vs baseline: 1.0198x; 1.0198x over previous
#include <cuda_runtime.h>
#include <math.h>

#define Nn 19
#define PADA 21      // eig kernel pad (conflict-free: gcd(21,32)=1)
#define PADG 20      // Gt row pad in dense (5 float4 per row)
#define ZPAD 68      // Z row stride: 16B-aligned, 3-way max LN conflicts
#define PADW 84      // W stage pad: 16B-aligned rows, conflict-free LDS.128
#define KE 16
#define Dd 64
#define Tt 1024
#define Bb 16
#define Gg (Bb*Tt)   // 16384 graphs
#define NSWEEP 5     // fixed: 4 fails accuracy (1.7e-3); adaptive 4..7 is slower
#define ALPHA_C 0.05f
#define HOPC 0.475f  // (1-alpha)/K
#define LN_EPS 1e-5f

// scratch (allocation-free rule: __device__ globals)
__device__ float g_G[(size_t)Gg*Nn*Nn];       // fused propagation operator G^T
__device__ float g_pe[(size_t)Gg*Nn*KE];      // ~19.9 MB

__device__ __forceinline__ float softplusf(float x){
    return fmaxf(x, 0.0f) + log1pf(expf(-fabsf(x)));
}

// ---------------------------------------------------------------------------
// Kernel A: per-graph (one warp each): a_norm -> G (transposed, fused 2-hop)
// + symmetrized Laplacian + fixed 5-sweep Jacobi + PE extraction.
// ---------------------------------------------------------------------------
__global__ void __launch_bounds__(256) eig_kernel(
    const float* __restrict__ adjacency,
    const float* __restrict__ edge_w_p,
    const float* __restrict__ edge_b_p)
{
    __shared__ float smem[8*(2*Nn*PADA + 96)];
    const int w = threadIdx.x >> 5;
    const int l = threadIdx.x & 31;
    const int g = blockIdx.x*8 + w;

    float* M   = smem + w*(2*Nn*PADA + 96);   // adj -> identity -> EVEC
    float* V   = M + Nn*PADA;                 // w -> a_norm -> lapS -> diag
    float* AUX = V + Nn*PADA;
    float* CS  = AUX;                         // 9 cosines
    float* SS  = AUX + 9;                     // 9 sines
    float* DIS = AUX + 18;                    // 19
    int*   ORD = (int*)(AUX + 40);            // 16
    float* SGN = AUX + 56;                    // 16
    int*   PSi = (int*)(AUX + 72);            // 9 p-indices (per round)
    int*   QSi = (int*)(AUX + 81);            // 9 q-indices

    const float ew = edge_w_p[0];
    const float eb = edge_b_p[0];
    const float* adj = adjacency + (size_t)g*Nn*Nn;

    for (int i = l; i < Nn*Nn; i += 32)
        M[(i/Nn)*PADA + (i%Nn)] = adj[i];
    __syncwarp();

    for (int i = l; i < Nn*Nn; i += 32){
        int r = i/Nn, c = i%Nn;
        float a = M[r*PADA + c];
        V[r*PADA + c] = (a > 0.0f) ? softplusf(a*ew + eb) : 0.0f;
    }
    __syncwarp();
    if (l < Nn){
        if (!(M[l*PADA + l] > 0.0f)) V[l*PADA + l] += 1.0f;
    }
    __syncwarp();

    if (l < Nn){
        float dsum = 0.0f;
        #pragma unroll
        for (int i = 0; i < Nn; i++) dsum += V[i*PADA + l];
        DIS[l] = (dsum > 0.0f) ? rsqrtf(fmaxf(dsum, 1e-30f)) : 0.0f;
    }
    __syncwarp();

    // a_norm in place: V = dis_r * V * dis_c
    for (int i = l; i < Nn*Nn; i += 32){
        int r = i/Nn, c = i%Nn;
        V[r*PADA + c] = DIS[r]*V[r*PADA + c]*DIS[c];
    }
    __syncwarp();

    // G^T to global: Gt[n,i] = a*(i==n) + C*(A[i,n] + (A^2)[i,n])
    {
        float* gG = g_G + (size_t)g*Nn*Nn;
        for (int e = l; e < Nn*Nn; e += 32){
            int n = e/Nn, i = e - n*Nn;
            float s = 0.0f;
            #pragma unroll
            for (int j = 0; j < Nn; j++) s += V[i*PADA + j]*V[j*PADA + n];
            float val = HOPC*(V[i*PADA + n] + s);
            if (i == n) val += ALPHA_C;
            gG[e] = val;
        }
    }
    __syncwarp();

    // PE normalization: deg = max(row sums of raw adj, 1e-6)
    if (l < Nn){
        float dsum = 0.0f;
        #pragma unroll
        for (int j = 0; j < Nn; j++) dsum += M[l*PADA + j];
        DIS[l] = rsqrtf(fmaxf(dsum, 1e-6f));
    }
    __syncwarp();

    for (int i = l; i < Nn*Nn; i += 32){
        int r = i/Nn, c = i%Nn;
        float an = 0.5f * DIS[r]*DIS[c] * (M[r*PADA + c] + M[c*PADA + r]);
        V[r*PADA + c] = ((r == c) ? (1.0f + 1e-5f) : 0.0f) - an;
    }
    __syncwarp();

    for (int i = l; i < Nn*Nn; i += 32){
        int r = i/Nn, c = i%Nn;
        M[r*PADA + c] = (r == c) ? 1.0f : 0.0f;
    }
    __syncwarp();

    // per-lane round-invariant task descriptors (offsets, not pointers)
    int  cOff[11];   // (m? M : V) row base, relative to M
    int  cK[11];     // k-1
    bool cValid[11];
    #pragma unroll
    for (int it = 0; it < 11; ++it){
        int t0 = l + 32*it;
        cValid[it] = (t0 < 2*9*Nn);
        int tt = cValid[it] ? t0 : 0;
        int m = tt / (9*Nn);
        int u = tt % (9*Nn);
        cK[it]   = u / Nn;
        cOff[it] = (m ? 0 : Nn*PADA) + (u % Nn)*PADA;
    }
    int  rK[6], rJ[6];
    bool rValid[6];
    #pragma unroll
    for (int it = 0; it < 6; ++it){
        int t0 = l + 32*it;
        rValid[it] = (t0 < 9*Nn);
        int tt = rValid[it] ? t0 : 0;
        rK[it] = tt / Nn;
        rJ[it] = tt % Nn;
    }

    for (int sweep = 0; sweep < NSWEEP; ++sweep){
        for (int r = 0; r < Nn; r++){
            if (l >= 1 && l <= 9){
                int k = l;
                int p = r + k; if (p >= Nn) p -= Nn;
                int q = r - k; if (q < 0)  q += Nn;
                float app = V[p*PADA + p];
                float aqq = V[q*PADA + q];
                float apq = V[p*PADA + q];
                float c = 1.0f, s = 0.0f;
                if (fabsf(apq) > 1e-30f){
                    float tau = (aqq - app) / (2.0f*apq);
                    float t = 1.0f / (fabsf(tau) + sqrtf(1.0f + tau*tau));
                    if (tau < 0.0f) t = -t;
                    c = rsqrtf(1.0f + t*t);
                    s = t*c;
                }
                CS[k-1] = c; SS[k-1] = s;
                PSi[k-1] = p; QSi[k-1] = q;
            }
            __syncwarp();
            #pragma unroll
            for (int it = 0; it < 11; ++it){
                if (cValid[it]){
                    int k = cK[it];
                    int p = PSi[k], q = QSi[k];
                    float c = CS[k], s = SS[k];
                    float* base = M + cOff[it];
                    float vp = base[p];
                    float vq = base[q];
                    base[p] = c*vp - s*vq;
                    base[q] = s*vp + c*vq;
                }
            }
            __syncwarp();
            #pragma unroll
            for (int it = 0; it < 6; ++it){
                if (rValid[it]){
                    int k = rK[it], j = rJ[it];
                    int p = PSi[k], q = QSi[k];
                    float c = CS[k], s = SS[k];
                    float vp = V[p*PADA + j];
                    float vq = V[q*PADA + j];
                    V[p*PADA + j] = c*vp - s*vq;
                    V[q*PADA + j] = s*vp + c*vq;
                }
            }
            __syncwarp();
        }
    }

    if (l < Nn){
        float dv = V[l*PADA + l];
        int rank = 0;
        #pragma unroll
        for (int j = 0; j < Nn; j++){
            float dj = V[j*PADA + j];
            rank += (dj < dv) || (dj == dv && j < l);
        }
        if (rank < KE) ORD[rank] = l;
    }
    __syncwarp();
    if (l < KE){
        int i = ORD[l];
        float sum = 0.0f;
        #pragma unroll
        for (int n = 0; n < Nn; n++) sum += M[n*PADA + i];
        SGN[l] = (sum > 0.0f) ? 1.0f : ((sum < 0.0f) ? -1.0f : 1.0f);
    }
    __syncwarp();
    {
        float* gp = g_pe + (size_t)g*Nn*KE;
        for (int t0 = l; t0 < Nn*KE; t0 += 32){
            int n = t0 / KE, m = t0 % KE;
            float v = M[n*PADA + ORD[m]] * SGN[m];
            if (isnan(v)) v = 0.0f;
            else if (isinf(v)) v = (v > 0.0f) ? 1.0f : -1.0f;
            gp[t0] = v;
        }
    }
}

// ---------------------------------------------------------------------------
// Kernel B: CTA-per-graph fused SSGConv0 -> LN0 -> SSGConv1 + res -> LN1.
// Weights staged in shared; wreg filled in 2 passes (unroll 1) to cap
// register pressure; acc[10] compile-time indexed (half1 uses dummy row 19).
// __launch_bounds__(128,5) pins 5 CTAs/SM. (R13 version, measured 461us.)
// ---------------------------------------------------------------------------
__global__ void __launch_bounds__(128, 5) dense_kernel(
    const float* __restrict__ features,
    const float* __restrict__ W0, const float* __restrict__ b0,
    const float* __restrict__ W1, const float* __restrict__ b1,
    const float* __restrict__ ln0g, const float* __restrict__ ln0b,
    const float* __restrict__ ln1g, const float* __restrict__ ln1b,
    float* __restrict__ out)
{
    __shared__ __align__(16) float Gt[20*PADG];   // 20 rows (row 19 zeroed)
    __shared__ __align__(16) float XC[20*80];     // x|pe; reused as h1 (20xZPAD)
    __shared__ __align__(16) float Z0[20*ZPAD];
    __shared__ __align__(16) float Z1[20*ZPAD];
    __shared__ __align__(16) float SW[64*PADW];   // staged weights (W0, then W1)
    __shared__ float MU[20], RS[20];

    const int g = blockIdx.x;
    const int b = g >> 10;
    const int t = g & 1023;
    const int tid = threadIdx.x;

    // load G^T (zero pad col and dummy row 19)
    {
        const float* gG = g_G + (size_t)g*Nn*Nn;
        for (int e = tid; e < Nn*Nn; e += 128)
            Gt[(e/Nn)*PADG + (e%Nn)] = gG[e];
        if (tid < 20) Gt[tid*PADG + Nn] = 0.0f;
        if (tid < PADG) Gt[Nn*PADG + tid] = 0.0f;
    }
    // stage W0 (64x80) coalesced into SW rows of stride 84
    for (int i = tid; i < 64*80; i += 128){
        int r = i / 80, c = i - r*80;
        SW[r*PADW + c] = W0[i];
    }
    // load x: XC[n][0:64] = features[b, n, t, :]
    for (int i = tid; i < Nn*64; i += 128){
        int n = i >> 6, dd = i & 63;
        XC[n*80 + dd] = features[((size_t)((b*Nn + n)*Tt + t))*64 + dd];
    }
    // load pe: XC[n][64:80]
    {
        const float* gp = g_pe + (size_t)g*Nn*KE;
        for (int i = tid; i < Nn*KE; i += 128){
            int n = i / KE, m = i % KE;
            XC[n*80 + 64 + m] = gp[i];
        }
    }
    __syncthreads();

    const int d    = tid & 63;
    const int half = tid >> 6;
    const int nb   = half*10;     // nodes nb..nb+9 (row 19 is scratch)

    // ---- GEMM0: Z0 = XC @ W0^T  (2 passes of 40 cols; wreg from smem) ----
    {
        float acc[10];
        #pragma unroll
        for (int m = 0; m < 10; m++) acc[m] = 0.0f;
        #pragma unroll 1
        for (int pass = 0; pass < 2; ++pass){
            float wreg[40];
            #pragma unroll
            for (int j4 = 0; j4 < 10; j4++){
                float4 v = *reinterpret_cast<const float4*>(SW + d*PADW + pass*40 + j4*4);
                wreg[j4*4+0] = v.x; wreg[j4*4+1] = v.y;
                wreg[j4*4+2] = v.z; wreg[j4*4+3] = v.w;
            }
            #pragma unroll
            for (int m = 0; m < 10; m++){
                const float4* xr = reinterpret_cast<const float4*>(XC + (nb+m)*80 + pass*40);
                float a = 0.0f;
                #pragma unroll
                for (int f4 = 0; f4 < 10; f4++){
                    float4 x = xr[f4];
                    a += x.x*wreg[f4*4+0] + x.y*wreg[f4*4+1]
                       + x.z*wreg[f4*4+2] + x.w*wreg[f4*4+3];
                }
                acc[m] += a;
            }
        }
        #pragma unroll
        for (int m = 0; m < 10; m++) Z0[(nb+m)*ZPAD + d] = acc[m];
    }
    __syncthreads();

    // stage W1 (64x64) into SW (overwrites W0; consumers re-read after LN0 sync)
    for (int i = tid; i < 64*64; i += 128){
        int r = i >> 6, c = i & 63;
        SW[r*PADW + c] = W1[i];
    }

    // ---- prop0: Z1 = G^T Z0 + b0 ----
    {
        float zc[20];
        #pragma unroll
        for (int i = 0; i < Nn; i++) zc[i] = Z0[i*ZPAD + d];
        zc[19] = 0.0f;
        float bb = b0[d];
        #pragma unroll
        for (int m = 0; m < 10; m++){
            int n = nb + m;
            const float4* gr = reinterpret_cast<const float4*>(Gt + n*PADG);
            float4 g0 = gr[0], g1 = gr[1], g2 = gr[2], g3 = gr[3], g4 = gr[4];
            float acc =
                g0.x*zc[0]  + g0.y*zc[1]  + g0.z*zc[2]  + g0.w*zc[3]
              + g1.x*zc[4]  + g1.y*zc[5]  + g1.z*zc[6]  + g1.w*zc[7]
              + g2.x*zc[8]  + g2.y*zc[9]  + g2.z*zc[10] + g2.w*zc[11]
              + g3.x*zc[12] + g3.y*zc[13] + g3.z*zc[14] + g3.w*zc[15]
              + g4.x*zc[16] + g4.y*zc[17] + g4.z*zc[18] + g4.w*zc[19];
            Z1[n*ZPAD + d] = acc + bb;
        }
    }
    __syncthreads();

    // ---- LN0 stats on Z1 (stride-68 -> 3-way conflicts max) ----
    if (tid < Nn){
        float mu = 0.0f;
        #pragma unroll
        for (int j = 0; j < 64; j++) mu += Z1[tid*ZPAD + j];
        mu *= (1.0f/64.0f);
        float var = 0.0f;
        #pragma unroll
        for (int j = 0; j < 64; j++){ float dv = Z1[tid*ZPAD + j] - mu; var += dv*dv; }
        var *= (1.0f/64.0f);
        MU[tid] = mu; RS[tid] = rsqrtf(var + LN_EPS);
    }
    if (tid == Nn){ MU[19] = 0.0f; RS[19] = 0.0f; }  // keep scratch row finite
    __syncthreads();
    // LN0 apply -> Z0 (GEMM1 input AND residual)
    {
        float gg = ln0g[d], bbb = ln0b[d];
        #pragma unroll
        for (int m = 0; m < 10; m++){
            int n = nb + m;
            Z0[n*ZPAD + d] = (Z1[n*ZPAD + d] - MU[n])*RS[n]*gg + bbb;
        }
    }
    __syncthreads();

    // ---- GEMM1: Z1 = Z0 @ W1^T  (2 passes of 32 cols) ----
    {
        float acc[10];
        #pragma unroll
        for (int m = 0; m < 10; m++) acc[m] = 0.0f;
        #pragma unroll 1
        for (int pass = 0; pass < 2; ++pass){
            float wreg[32];
            #pragma unroll
            for (int j4 = 0; j4 < 8; j4++){
                float4 v = *reinterpret_cast<const float4*>(SW + d*PADW + pass*32 + j4*4);
                wreg[j4*4+0] = v.x; wreg[j4*4+1] = v.y;
                wreg[j4*4+2] = v.z; wreg[j4*4+3] = v.w;
            }
            #pragma unroll
            for (int m = 0; m < 10; m++){
                const float4* xr = reinterpret_cast<const float4*>(Z0 + (nb+m)*ZPAD + pass*32);
                float a = 0.0f;
                #pragma unroll
                for (int f4 = 0; f4 < 8; f4++){
                    float4 x = xr[f4];
                    a += x.x*wreg[f4*4+0] + x.y*wreg[f4*4+1]
                       + x.z*wreg[f4*4+2] + x.w*wreg[f4*4+3];
                }
                acc[m] += a;
            }
        }
        #pragma unroll
        for (int m = 0; m < 10; m++) Z1[(nb+m)*ZPAD + d] = acc[m];
    }
    __syncthreads();

    // ---- prop1 + residual: h1 = G^T Z1 + b1 + Z0  -> XC (stride ZPAD) ----
    {
        float zc[20];
        #pragma unroll
        for (int i = 0; i < Nn; i++) zc[i] = Z1[i*ZPAD + d];
        zc[19] = 0.0f;
        float bb = b1[d];
        #pragma unroll
        for (int m = 0; m < 10; m++){
            int n = nb + m;
            const float4* gr = reinterpret_cast<const float4*>(Gt + n*PADG);
            float4 g0 = gr[0], g1 = gr[1], g2 = gr[2], g3 = gr[3], g4 = gr[4];
            float acc =
                g0.x*zc[0]  + g0.y*zc[1]  + g0.z*zc[2]  + g0.w*zc[3]
              + g1.x*zc[4]  + g1.y*zc[5]  + g1.z*zc[6]  + g1.w*zc[7]
              + g2.x*zc[8]  + g2.y*zc[9]  + g2.z*zc[10] + g2.w*zc[11]
              + g3.x*zc[12] + g3.y*zc[13] + g3.z*zc[14] + g3.w*zc[15]
              + g4.x*zc[16] + g4.y*zc[17] + g4.z*zc[18] + g4.w*zc[19];
            XC[n*ZPAD + d] = acc + bb + Z0[n*ZPAD + d];
        }
    }
    __syncthreads();

    // ---- LN1 stats on XC ----
    if (tid < Nn){
        float mu = 0.0f;
        #pragma unroll
        for (int j = 0; j < 64; j++) mu += XC[tid*ZPAD + j];
        mu *= (1.0f/64.0f);
        float var = 0.0f;
        #pragma unroll
        for (int j = 0; j < 64; j++){ float dv = XC[tid*ZPAD + j] - mu; var += dv*dv; }
        var *= (1.0f/64.0f);
        MU[tid] = mu; RS[tid] = rsqrtf(var + LN_EPS);
    }
    __syncthreads();
    {
        float gg = ln1g[d], bbb = ln1b[d];
        #pragma unroll
        for (int m = 0; m < 10; m++){
            int n = nb + m;
            if (n < Nn){
                float v = (XC[n*ZPAD + d] - MU[n])*RS[n]*gg + bbb;
                out[((size_t)((b*Nn + n)*Tt + t))*64 + d] = v;
            }
        }
    }
}

// ---------------------------------------------------------------------------
extern "C" void kernel_launch(void* const* d_in, const int* in_sizes, int n_in,
                              void* d_out, int out_size)
{
    const float* features  = (const float*)d_in[0];
    const float* adjacency = (const float*)d_in[1];
    const float* edge_w    = (const float*)d_in[2];
    const float* edge_b    = (const float*)d_in[3];
    const float* gnn0_W    = (const float*)d_in[4];
    const float* gnn0_b    = (const float*)d_in[5];
    const float* gnn1_W    = (const float*)d_in[6];
    const float* gnn1_b    = (const float*)d_in[7];
    const float* ln0_g     = (const float*)d_in[8];
    const float* ln0_b     = (const float*)d_in[9];
    const float* ln1_g     = (const float*)d_in[10];
    const float* ln1_b     = (const float*)d_in[11];
    float* out = (float*)d_out;

    eig_kernel<<<Gg/8, 256>>>(adjacency, edge_w, edge_b);
    dense_kernel<<<Gg, 128>>>(features, gnn0_W, gnn0_b, gnn1_W, gnn1_b,
                              ln0_g, ln0_b, ln1_g, ln1_b, out);
}

// round 16
// speedup vs baseline: 1.1098x; 1.0883x over previous
#include <cuda_runtime.h>
#include <math.h>

#define Nn 19
#define PADA 21      // eig kernel pad (conflict-free: gcd(21,32)=1)
#define PADG 20      // Gt row pad in dense (5 float4 per row)
#define ZPAD 68      // Z row stride: 16B-aligned, 3-way max LN conflicts
#define PADW 84      // W stage pad: 16B-aligned rows, conflict-free LDS.128
#define KE 16
#define Dd 64
#define Tt 1024
#define Bb 16
#define Gg (Bb*Tt)   // 16384 graphs
#define NSWEEP 5     // fixed: 4 fails accuracy (1.7e-3); adaptive 4..7 is slower
#define SKIP_TOL 1e-7f  // rotations below this are fp32-invisible; skip smem work
#define ALPHA_C 0.05f
#define HOPC 0.475f  // (1-alpha)/K
#define LN_EPS 1e-5f

// scratch (allocation-free rule: __device__ globals)
__device__ float g_G[(size_t)Gg*Nn*Nn];       // fused propagation operator G^T
__device__ float g_pe[(size_t)Gg*Nn*KE];      // ~19.9 MB

__device__ __forceinline__ float softplusf(float x){
    return fmaxf(x, 0.0f) + log1pf(expf(-fabsf(x)));
}

// ---------------------------------------------------------------------------
// Kernel A: per-graph (one warp each): a_norm -> G (transposed, fused 2-hop)
// + symmetrized Laplacian + fixed 5-sweep Jacobi + PE extraction.
// p,q computed in ALU (idle pipe); smem pipe is the bottleneck. Near-identity
// rotations (|apq| < SKIP_TOL) publish s=0 and all task lanes skip their
// LDS/STS entirely, shrinking wavefronts in late sweeps.
// ---------------------------------------------------------------------------
__global__ void __launch_bounds__(256) eig_kernel(
    const float* __restrict__ adjacency,
    const float* __restrict__ edge_w_p,
    const float* __restrict__ edge_b_p)
{
    __shared__ float smem[8*(2*Nn*PADA + 96)];
    const int w = threadIdx.x >> 5;
    const int l = threadIdx.x & 31;
    const int g = blockIdx.x*8 + w;

    float* M   = smem + w*(2*Nn*PADA + 96);   // adj -> identity -> EVEC
    float* V   = M + Nn*PADA;                 // w -> a_norm -> lapS -> diag
    float* AUX = V + Nn*PADA;
    float* CS  = AUX;                         // 9 cosines
    float* SS  = AUX + 9;                     // 9 sines
    float* DIS = AUX + 18;                    // 19
    int*   ORD = (int*)(AUX + 40);            // 16
    float* SGN = AUX + 56;                    // 16

    const float ew = edge_w_p[0];
    const float eb = edge_b_p[0];
    const float* adj = adjacency + (size_t)g*Nn*Nn;

    for (int i = l; i < Nn*Nn; i += 32)
        M[(i/Nn)*PADA + (i%Nn)] = adj[i];
    __syncwarp();

    for (int i = l; i < Nn*Nn; i += 32){
        int r = i/Nn, c = i%Nn;
        float a = M[r*PADA + c];
        V[r*PADA + c] = (a > 0.0f) ? softplusf(a*ew + eb) : 0.0f;
    }
    __syncwarp();
    if (l < Nn){
        if (!(M[l*PADA + l] > 0.0f)) V[l*PADA + l] += 1.0f;
    }
    __syncwarp();

    if (l < Nn){
        float dsum = 0.0f;
        #pragma unroll
        for (int i = 0; i < Nn; i++) dsum += V[i*PADA + l];
        DIS[l] = (dsum > 0.0f) ? rsqrtf(fmaxf(dsum, 1e-30f)) : 0.0f;
    }
    __syncwarp();

    // a_norm in place: V = dis_r * V * dis_c
    for (int i = l; i < Nn*Nn; i += 32){
        int r = i/Nn, c = i%Nn;
        V[r*PADA + c] = DIS[r]*V[r*PADA + c]*DIS[c];
    }
    __syncwarp();

    // G^T to global: Gt[n,i] = a*(i==n) + C*(A[i,n] + (A^2)[i,n])
    {
        float* gG = g_G + (size_t)g*Nn*Nn;
        for (int e = l; e < Nn*Nn; e += 32){
            int n = e/Nn, i = e - n*Nn;
            float s = 0.0f;
            #pragma unroll
            for (int j = 0; j < Nn; j++) s += V[i*PADA + j]*V[j*PADA + n];
            float val = HOPC*(V[i*PADA + n] + s);
            if (i == n) val += ALPHA_C;
            gG[e] = val;
        }
    }
    __syncwarp();

    // PE normalization: deg = max(row sums of raw adj, 1e-6)
    if (l < Nn){
        float dsum = 0.0f;
        #pragma unroll
        for (int j = 0; j < Nn; j++) dsum += M[l*PADA + j];
        DIS[l] = rsqrtf(fmaxf(dsum, 1e-6f));
    }
    __syncwarp();

    for (int i = l; i < Nn*Nn; i += 32){
        int r = i/Nn, c = i%Nn;
        float an = 0.5f * DIS[r]*DIS[c] * (M[r*PADA + c] + M[c*PADA + r]);
        V[r*PADA + c] = ((r == c) ? (1.0f + 1e-5f) : 0.0f) - an;
    }
    __syncwarp();

    for (int i = l; i < Nn*Nn; i += 32){
        int r = i/Nn, c = i%Nn;
        M[r*PADA + c] = (r == c) ? 1.0f : 0.0f;
    }
    __syncwarp();

    // per-lane round-invariant task descriptors (offsets, not pointers)
    int  cOff[11];   // (m? M : V) row base, relative to M
    int  cK[11];     // k (1..9)
    bool cValid[11];
    #pragma unroll
    for (int it = 0; it < 11; ++it){
        int t0 = l + 32*it;
        cValid[it] = (t0 < 2*9*Nn);
        int tt = cValid[it] ? t0 : 0;
        int m = tt / (9*Nn);
        int u = tt % (9*Nn);
        cK[it]   = u / Nn + 1;
        cOff[it] = (m ? 0 : Nn*PADA) + (u % Nn)*PADA;
    }
    int  rK[6], rJ[6];
    bool rValid[6];
    #pragma unroll
    for (int it = 0; it < 6; ++it){
        int t0 = l + 32*it;
        rValid[it] = (t0 < 9*Nn);
        int tt = rValid[it] ? t0 : 0;
        rK[it] = tt / Nn + 1;
        rJ[it] = tt % Nn;
    }

    for (int sweep = 0; sweep < NSWEEP; ++sweep){
        for (int r = 0; r < Nn; r++){
            if (l >= 1 && l <= 9){
                int k = l;
                int p = r + k; if (p >= Nn) p -= Nn;
                int q = r - k; if (q < 0)  q += Nn;
                float app = V[p*PADA + p];
                float aqq = V[q*PADA + q];
                float apq = V[p*PADA + q];
                float c = 1.0f, s = 0.0f;
                if (fabsf(apq) > SKIP_TOL){
                    float tau = (aqq - app) / (2.0f*apq);
                    float t = 1.0f / (fabsf(tau) + sqrtf(1.0f + tau*tau));
                    if (tau < 0.0f) t = -t;
                    c = rsqrtf(1.0f + t*t);
                    s = t*c;
                }
                CS[k-1] = c; SS[k-1] = s;
            }
            __syncwarp();
            // column phase on MAT (B = A*J) and EVEC (V = V*J); skip s==0
            #pragma unroll
            for (int it = 0; it < 11; ++it){
                if (cValid[it]){
                    int k = cK[it];
                    float s = SS[k-1];
                    if (s != 0.0f){
                        float c = CS[k-1];
                        int p = r + k; if (p >= Nn) p -= Nn;
                        int q = r - k; if (q < 0)  q += Nn;
                        float* base = M + cOff[it];
                        float vp = base[p];
                        float vq = base[q];
                        base[p] = c*vp - s*vq;
                        base[q] = s*vp + c*vq;
                    }
                }
            }
            __syncwarp();
            // row phase on MAT (A' = J^T * B); skip s==0
            #pragma unroll
            for (int it = 0; it < 6; ++it){
                if (rValid[it]){
                    int k = rK[it];
                    float s = SS[k-1];
                    if (s != 0.0f){
                        float c = CS[k-1];
                        int j = rJ[it];
                        int p = r + k; if (p >= Nn) p -= Nn;
                        int q = r - k; if (q < 0)  q += Nn;
                        float vp = V[p*PADA + j];
                        float vq = V[q*PADA + j];
                        V[p*PADA + j] = c*vp - s*vq;
                        V[q*PADA + j] = s*vp + c*vq;
                    }
                }
            }
            __syncwarp();
        }
    }

    if (l < Nn){
        float dv = V[l*PADA + l];
        int rank = 0;
        #pragma unroll
        for (int j = 0; j < Nn; j++){
            float dj = V[j*PADA + j];
            rank += (dj < dv) || (dj == dv && j < l);
        }
        if (rank < KE) ORD[rank] = l;
    }
    __syncwarp();
    if (l < KE){
        int i = ORD[l];
        float sum = 0.0f;
        #pragma unroll
        for (int n = 0; n < Nn; n++) sum += M[n*PADA + i];
        SGN[l] = (sum > 0.0f) ? 1.0f : ((sum < 0.0f) ? -1.0f : 1.0f);
    }
    __syncwarp();
    {
        float* gp = g_pe + (size_t)g*Nn*KE;
        for (int t0 = l; t0 < Nn*KE; t0 += 32){
            int n = t0 / KE, m = t0 % KE;
            float v = M[n*PADA + ORD[m]] * SGN[m];
            if (isnan(v)) v = 0.0f;
            else if (isinf(v)) v = (v > 0.0f) ? 1.0f : -1.0f;
            gp[t0] = v;
        }
    }
}

// ---------------------------------------------------------------------------
// Kernel B: CTA-per-graph fused SSGConv0 -> LN0 -> SSGConv1 + res -> LN1.
// (R13 version, measured 461-464us twice; unchanged.)
// ---------------------------------------------------------------------------
__global__ void __launch_bounds__(128, 5) dense_kernel(
    const float* __restrict__ features,
    const float* __restrict__ W0, const float* __restrict__ b0,
    const float* __restrict__ W1, const float* __restrict__ b1,
    const float* __restrict__ ln0g, const float* __restrict__ ln0b,
    const float* __restrict__ ln1g, const float* __restrict__ ln1b,
    float* __restrict__ out)
{
    __shared__ __align__(16) float Gt[20*PADG];   // 20 rows (row 19 zeroed)
    __shared__ __align__(16) float XC[20*80];     // x|pe; reused as h1 (20xZPAD)
    __shared__ __align__(16) float Z0[20*ZPAD];
    __shared__ __align__(16) float Z1[20*ZPAD];
    __shared__ __align__(16) float SW[64*PADW];   // staged weights (W0, then W1)
    __shared__ float MU[20], RS[20];

    const int g = blockIdx.x;
    const int b = g >> 10;
    const int t = g & 1023;
    const int tid = threadIdx.x;

    // load G^T (zero pad col and dummy row 19)
    {
        const float* gG = g_G + (size_t)g*Nn*Nn;
        for (int e = tid; e < Nn*Nn; e += 128)
            Gt[(e/Nn)*PADG + (e%Nn)] = gG[e];
        if (tid < 20) Gt[tid*PADG + Nn] = 0.0f;
        if (tid < PADG) Gt[Nn*PADG + tid] = 0.0f;
    }
    // stage W0 (64x80) coalesced into SW rows of stride 84
    for (int i = tid; i < 64*80; i += 128){
        int r = i / 80, c = i - r*80;
        SW[r*PADW + c] = W0[i];
    }
    // load x: XC[n][0:64] = features[b, n, t, :]
    for (int i = tid; i < Nn*64; i += 128){
        int n = i >> 6, dd = i & 63;
        XC[n*80 + dd] = features[((size_t)((b*Nn + n)*Tt + t))*64 + dd];
    }
    // load pe: XC[n][64:80]
    {
        const float* gp = g_pe + (size_t)g*Nn*KE;
        for (int i = tid; i < Nn*KE; i += 128){
            int n = i / KE, m = i % KE;
            XC[n*80 + 64 + m] = gp[i];
        }
    }
    __syncthreads();

    const int d    = tid & 63;
    const int half = tid >> 6;
    const int nb   = half*10;     // nodes nb..nb+9 (row 19 is scratch)

    // ---- GEMM0: Z0 = XC @ W0^T  (2 passes of 40 cols; wreg from smem) ----
    {
        float acc[10];
        #pragma unroll
        for (int m = 0; m < 10; m++) acc[m] = 0.0f;
        #pragma unroll 1
        for (int pass = 0; pass < 2; ++pass){
            float wreg[40];
            #pragma unroll
            for (int j4 = 0; j4 < 10; j4++){
                float4 v = *reinterpret_cast<const float4*>(SW + d*PADW + pass*40 + j4*4);
                wreg[j4*4+0] = v.x; wreg[j4*4+1] = v.y;
                wreg[j4*4+2] = v.z; wreg[j4*4+3] = v.w;
            }
            #pragma unroll
            for (int m = 0; m < 10; m++){
                const float4* xr = reinterpret_cast<const float4*>(XC + (nb+m)*80 + pass*40);
                float a = 0.0f;
                #pragma unroll
                for (int f4 = 0; f4 < 10; f4++){
                    float4 x = xr[f4];
                    a += x.x*wreg[f4*4+0] + x.y*wreg[f4*4+1]
                       + x.z*wreg[f4*4+2] + x.w*wreg[f4*4+3];
                }
                acc[m] += a;
            }
        }
        #pragma unroll
        for (int m = 0; m < 10; m++) Z0[(nb+m)*ZPAD + d] = acc[m];
    }
    __syncthreads();

    // stage W1 (64x64) into SW (overwrites W0; consumers re-read after LN0 sync)
    for (int i = tid; i < 64*64; i += 128){
        int r = i >> 6, c = i & 63;
        SW[r*PADW + c] = W1[i];
    }

    // ---- prop0: Z1 = G^T Z0 + b0 ----
    {
        float zc[20];
        #pragma unroll
        for (int i = 0; i < Nn; i++) zc[i] = Z0[i*ZPAD + d];
        zc[19] = 0.0f;
        float bb = b0[d];
        #pragma unroll
        for (int m = 0; m < 10; m++){
            int n = nb + m;
            const float4* gr = reinterpret_cast<const float4*>(Gt + n*PADG);
            float4 g0 = gr[0], g1 = gr[1], g2 = gr[2], g3 = gr[3], g4 = gr[4];
            float acc =
                g0.x*zc[0]  + g0.y*zc[1]  + g0.z*zc[2]  + g0.w*zc[3]
              + g1.x*zc[4]  + g1.y*zc[5]  + g1.z*zc[6]  + g1.w*zc[7]
              + g2.x*zc[8]  + g2.y*zc[9]  + g2.z*zc[10] + g2.w*zc[11]
              + g3.x*zc[12] + g3.y*zc[13] + g3.z*zc[14] + g3.w*zc[15]
              + g4.x*zc[16] + g4.y*zc[17] + g4.z*zc[18] + g4.w*zc[19];
            Z1[n*ZPAD + d] = acc + bb;
        }
    }
    __syncthreads();

    // ---- LN0 stats on Z1 (stride-68 -> 3-way conflicts max) ----
    if (tid < Nn){
        float mu = 0.0f;
        #pragma unroll
        for (int j = 0; j < 64; j++) mu += Z1[tid*ZPAD + j];
        mu *= (1.0f/64.0f);
        float var = 0.0f;
        #pragma unroll
        for (int j = 0; j < 64; j++){ float dv = Z1[tid*ZPAD + j] - mu; var += dv*dv; }
        var *= (1.0f/64.0f);
        MU[tid] = mu; RS[tid] = rsqrtf(var + LN_EPS);
    }
    if (tid == Nn){ MU[19] = 0.0f; RS[19] = 0.0f; }  // keep scratch row finite
    __syncthreads();
    // LN0 apply -> Z0 (GEMM1 input AND residual)
    {
        float gg = ln0g[d], bbb = ln0b[d];
        #pragma unroll
        for (int m = 0; m < 10; m++){
            int n = nb + m;
            Z0[n*ZPAD + d] = (Z1[n*ZPAD + d] - MU[n])*RS[n]*gg + bbb;
        }
    }
    __syncthreads();

    // ---- GEMM1: Z1 = Z0 @ W1^T  (2 passes of 32 cols) ----
    {
        float acc[10];
        #pragma unroll
        for (int m = 0; m < 10; m++) acc[m] = 0.0f;
        #pragma unroll 1
        for (int pass = 0; pass < 2; ++pass){
            float wreg[32];
            #pragma unroll
            for (int j4 = 0; j4 < 8; j4++){
                float4 v = *reinterpret_cast<const float4*>(SW + d*PADW + pass*32 + j4*4);
                wreg[j4*4+0] = v.x; wreg[j4*4+1] = v.y;
                wreg[j4*4+2] = v.z; wreg[j4*4+3] = v.w;
            }
            #pragma unroll
            for (int m = 0; m < 10; m++){
                const float4* xr = reinterpret_cast<const float4*>(Z0 + (nb+m)*ZPAD + pass*32);
                float a = 0.0f;
                #pragma unroll
                for (int f4 = 0; f4 < 8; f4++){
                    float4 x = xr[f4];
                    a += x.x*wreg[f4*4+0] + x.y*wreg[f4*4+1]
                       + x.z*wreg[f4*4+2] + x.w*wreg[f4*4+3];
                }
                acc[m] += a;
            }
        }
        #pragma unroll
        for (int m = 0; m < 10; m++) Z1[(nb+m)*ZPAD + d] = acc[m];
    }
    __syncthreads();

    // ---- prop1 + residual: h1 = G^T Z1 + b1 + Z0  -> XC (stride ZPAD) ----
    {
        float zc[20];
        #pragma unroll
        for (int i = 0; i < Nn; i++) zc[i] = Z1[i*ZPAD + d];
        zc[19] = 0.0f;
        float bb = b1[d];
        #pragma unroll
        for (int m = 0; m < 10; m++){
            int n = nb + m;
            const float4* gr = reinterpret_cast<const float4*>(Gt + n*PADG);
            float4 g0 = gr[0], g1 = gr[1], g2 = gr[2], g3 = gr[3], g4 = gr[4];
            float acc =
                g0.x*zc[0]  + g0.y*zc[1]  + g0.z*zc[2]  + g0.w*zc[3]
              + g1.x*zc[4]  + g1.y*zc[5]  + g1.z*zc[6]  + g1.w*zc[7]
              + g2.x*zc[8]  + g2.y*zc[9]  + g2.z*zc[10] + g2.w*zc[11]
              + g3.x*zc[12] + g3.y*zc[13] + g3.z*zc[14] + g3.w*zc[15]
              + g4.x*zc[16] + g4.y*zc[17] + g4.z*zc[18] + g4.w*zc[19];
            XC[n*ZPAD + d] = acc + bb + Z0[n*ZPAD + d];
        }
    }
    __syncthreads();

    // ---- LN1 stats on XC ----
    if (tid < Nn){
        float mu = 0.0f;
        #pragma unroll
        for (int j = 0; j < 64; j++) mu += XC[tid*ZPAD + j];
        mu *= (1.0f/64.0f);
        float var = 0.0f;
        #pragma unroll
        for (int j = 0; j < 64; j++){ float dv = XC[tid*ZPAD + j] - mu; var += dv*dv; }
        var *= (1.0f/64.0f);
        MU[tid] = mu; RS[tid] = rsqrtf(var + LN_EPS);
    }
    __syncthreads();
    {
        float gg = ln1g[d], bbb = ln1b[d];
        #pragma unroll
        for (int m = 0; m < 10; m++){
            int n = nb + m;
            if (n < Nn){
                float v = (XC[n*ZPAD + d] - MU[n])*RS[n]*gg + bbb;
                out[((size_t)((b*Nn + n)*Tt + t))*64 + d] = v;
            }
        }
    }
}

// ---------------------------------------------------------------------------
extern "C" void kernel_launch(void* const* d_in, const int* in_sizes, int n_in,
                              void* d_out, int out_size)
{
    const float* features  = (const float*)d_in[0];
    const float* adjacency = (const float*)d_in[1];
    const float* edge_w    = (const float*)d_in[2];
    const float* edge_b    = (const float*)d_in[3];
    const float* gnn0_W    = (const float*)d_in[4];
    const float* gnn0_b    = (const float*)d_in[5];
    const float* gnn1_W    = (const float*)d_in[6];
    const float* gnn1_b    = (const float*)d_in[7];
    const float* ln0_g     = (const float*)d_in[8];
    const float* ln0_b     = (const float*)d_in[9];
    const float* ln1_g     = (const float*)d_in[10];
    const float* ln1_b     = (const float*)d_in[11];
    float* out = (float*)d_out;

    eig_kernel<<<Gg/8, 256>>>(adjacency, edge_w, edge_b);
    dense_kernel<<<Gg, 128>>>(features, gnn0_W, gnn0_b, gnn1_W, gnn1_b,
                              ln0_g, ln0_b, ln1_g, ln1_b, out);
}

// round 17
// speedup vs baseline: 1.1979x; 1.0794x over previous
#include <cuda_runtime.h>
#include <math.h>

#define Nn 19
#define PADA 20      // eig pad: rows 16B-aligned for float4 row phases
#define PADG 20      // Gt row pad in dense (5 float4 per row)
#define ZPAD 68      // Z row stride: 16B-aligned, 3-way max LN conflicts
#define PADW 84      // W stage pad: 16B-aligned rows, conflict-free LDS.128
#define KE 16
#define Dd 64
#define Tt 1024
#define Bb 16
#define Gg (Bb*Tt)   // 16384 graphs
#define NSWEEP 5     // fixed: 4 fails accuracy (1.7e-3); adaptive 4..7 is slower
#define SKIP_TOL 1e-7f  // rotations below this are fp32-invisible; skip smem work
#define ALPHA_C 0.05f
#define HOPC 0.475f  // (1-alpha)/K
#define LN_EPS 1e-5f

#define WSM (2*Nn*PADA + 96)   // floats per warp slab: 2*380 + 96 = 856 (16B mult.)

// scratch (allocation-free rule: __device__ globals)
__device__ float g_G[(size_t)Gg*Nn*Nn];       // fused propagation operator G^T
__device__ float g_pe[(size_t)Gg*Nn*KE];      // ~19.9 MB

__device__ __forceinline__ float softplusf(float x){
    return fmaxf(x, 0.0f) + log1pf(expf(-fabsf(x)));
}

// ---------------------------------------------------------------------------
// Kernel A: per-graph (one warp each): a_norm -> G (transposed, fused 2-hop)
// + symmetrized Laplacian + 5-sweep Jacobi + PE extraction.
// Eigenvector matrix stored TRANSPOSED (MT): its column update M:=M*J becomes
// a row update MT:=J^T*MT -> float4. V's row phase also float4. V's column
// phase stays scalar. Round = rot -> V-col(6 it) -> {V-row|MT-row}(3 it).
// eig is issue-bound (smem bw at ~37%), so fewer instructions = time.
// ---------------------------------------------------------------------------
__global__ void __launch_bounds__(256) eig_kernel(
    const float* __restrict__ adjacency,
    const float* __restrict__ edge_w_p,
    const float* __restrict__ edge_b_p)
{
    __shared__ __align__(16) float smem[8*WSM];
    const int w = threadIdx.x >> 5;
    const int l = threadIdx.x & 31;
    const int g = blockIdx.x*8 + w;

    float* MT  = smem + w*WSM;                // raw adj -> identity -> EVEC^T
    float* V   = MT + Nn*PADA;                // w -> a_norm -> lapS -> diag
    float* AUX = V + Nn*PADA;
    float* CS  = AUX;                         // 9 cosines
    float* SS  = AUX + 9;                     // 9 sines
    float* DIS = AUX + 18;                    // 19
    int*   ORD = (int*)(AUX + 40);            // 16
    float* SGN = AUX + 56;                    // 16

    const float ew = edge_w_p[0];
    const float eb = edge_b_p[0];
    const float* adj = adjacency + (size_t)g*Nn*Nn;

    // 1. raw adjacency into MT (scratch use)
    for (int i = l; i < Nn*Nn; i += 32)
        MT[(i/Nn)*PADA + (i%Nn)] = adj[i];
    __syncwarp();

    // 2. edge transform
    for (int i = l; i < Nn*Nn; i += 32){
        int r = i/Nn, c = i%Nn;
        float a = MT[r*PADA + c];
        V[r*PADA + c] = (a > 0.0f) ? softplusf(a*ew + eb) : 0.0f;
    }
    __syncwarp();
    if (l < Nn){
        if (!(MT[l*PADA + l] > 0.0f)) V[l*PADA + l] += 1.0f;
    }
    __syncwarp();

    // 3. gcn_norm degrees (column sums)
    if (l < Nn){
        float dsum = 0.0f;
        #pragma unroll
        for (int i = 0; i < Nn; i++) dsum += V[i*PADA + l];
        DIS[l] = (dsum > 0.0f) ? rsqrtf(fmaxf(dsum, 1e-30f)) : 0.0f;
    }
    __syncwarp();

    // 4. a_norm in place
    for (int i = l; i < Nn*Nn; i += 32){
        int r = i/Nn, c = i%Nn;
        V[r*PADA + c] = DIS[r]*V[r*PADA + c]*DIS[c];
    }
    __syncwarp();

    // 5. G^T to global: Gt[n,i] = a*(i==n) + C*(A[i,n] + (A^2)[i,n])
    {
        float* gG = g_G + (size_t)g*Nn*Nn;
        for (int e = l; e < Nn*Nn; e += 32){
            int n = e/Nn, i = e - n*Nn;
            float s = 0.0f;
            #pragma unroll
            for (int j = 0; j < Nn; j++) s += V[i*PADA + j]*V[j*PADA + n];
            float val = HOPC*(V[i*PADA + n] + s);
            if (i == n) val += ALPHA_C;
            gG[e] = val;
        }
    }
    __syncwarp();

    // 6. PE normalization: deg = max(row sums of raw adj, 1e-6)
    if (l < Nn){
        float dsum = 0.0f;
        #pragma unroll
        for (int j = 0; j < Nn; j++) dsum += MT[l*PADA + j];
        DIS[l] = rsqrtf(fmaxf(dsum, 1e-6f));
    }
    __syncwarp();

    // 7. symmetrized Laplacian into V
    for (int i = l; i < Nn*Nn; i += 32){
        int r = i/Nn, c = i%Nn;
        float an = 0.5f * DIS[r]*DIS[c] * (MT[r*PADA + c] + MT[c*PADA + r]);
        V[r*PADA + c] = ((r == c) ? (1.0f + 1e-5f) : 0.0f) - an;
    }
    __syncwarp();

    // 8. MT := identity (transposed EVEC accumulator; identity is symmetric)
    for (int i = l; i < Nn*Nn; i += 32){
        int r = i/Nn, c = i%Nn;
        MT[r*PADA + c] = (r == c) ? 1.0f : 0.0f;
    }
    __syncwarp();

    // --- per-lane round-invariant task descriptors ---
    // V column phase: 171 tasks = {k=1..9} x {row i}: scalar scatter
    float* cRow[6];
    int    cK[6];
    bool   cValid[6];
    #pragma unroll
    for (int it = 0; it < 6; ++it){
        int t0 = l + 32*it;
        cValid[it] = (t0 < 9*Nn);
        int tt = cValid[it] ? t0 : 0;
        cK[it]  = tt / Nn + 1;
        cRow[it] = V + (tt % Nn)*PADA;
    }
    // combined row phase: 90 float4 tasks = {V,MT} x {k=1..9} x {5 col-chunks}
    float* rBase[3];
    int    rK[3];
    bool   rValid[3];
    #pragma unroll
    for (int it = 0; it < 3; ++it){
        int t0 = l + 32*it;
        rValid[it] = (t0 < 90);
        int tt = rValid[it] ? t0 : 0;
        int m = tt / 45;
        int u = tt % 45;
        rK[it]   = u / 5 + 1;
        rBase[it] = (m ? MT : V) + (u % 5)*4;
    }

    for (int sweep = 0; sweep < NSWEEP; ++sweep){
        for (int r = 0; r < Nn; r++){
            // rotation parameters (lanes 1..9)
            if (l >= 1 && l <= 9){
                int k = l;
                int p = r + k; if (p >= Nn) p -= Nn;
                int q = r - k; if (q < 0)  q += Nn;
                float app = V[p*PADA + p];
                float aqq = V[q*PADA + q];
                float apq = V[p*PADA + q];
                float c = 1.0f, s = 0.0f;
                if (fabsf(apq) > SKIP_TOL){
                    float tau = (aqq - app) / (2.0f*apq);
                    float t = 1.0f / (fabsf(tau) + sqrtf(1.0f + tau*tau));
                    if (tau < 0.0f) t = -t;
                    c = rsqrtf(1.0f + t*t);
                    s = t*c;
                }
                CS[k-1] = c; SS[k-1] = s;
            }
            __syncwarp();
            // V column phase (B = A*J): scalar, skip s==0
            #pragma unroll
            for (int it = 0; it < 6; ++it){
                if (cValid[it]){
                    int k = cK[it];
                    float s = SS[k-1];
                    if (s != 0.0f){
                        float c = CS[k-1];
                        int p = r + k; if (p >= Nn) p -= Nn;
                        int q = r - k; if (q < 0)  q += Nn;
                        float* row = cRow[it];
                        float vp = row[p];
                        float vq = row[q];
                        row[p] = c*vp - s*vq;
                        row[q] = s*vp + c*vq;
                    }
                }
            }
            __syncwarp();
            // combined float4 row phase: V (A' = J^T*B) and MT (J^T*MT)
            #pragma unroll
            for (int it = 0; it < 3; ++it){
                if (rValid[it]){
                    int k = rK[it];
                    float s = SS[k-1];
                    if (s != 0.0f){
                        float c = CS[k-1];
                        int p = r + k; if (p >= Nn) p -= Nn;
                        int q = r - k; if (q < 0)  q += Nn;
                        float* bp = rBase[it] + p*PADA;
                        float* bq = rBase[it] + q*PADA;
                        float4 vp = *reinterpret_cast<float4*>(bp);
                        float4 vq = *reinterpret_cast<float4*>(bq);
                        float4 np, nq;
                        np.x = c*vp.x - s*vq.x;  nq.x = s*vp.x + c*vq.x;
                        np.y = c*vp.y - s*vq.y;  nq.y = s*vp.y + c*vq.y;
                        np.z = c*vp.z - s*vq.z;  nq.z = s*vp.z + c*vq.z;
                        np.w = c*vp.w - s*vq.w;  nq.w = s*vp.w + c*vq.w;
                        *reinterpret_cast<float4*>(bp) = np;
                        *reinterpret_cast<float4*>(bq) = nq;
                    }
                }
            }
            __syncwarp();
        }
    }

    // rank eigenvalues ascending (stable), keep first 16
    if (l < Nn){
        float dv = V[l*PADA + l];
        int rank = 0;
        #pragma unroll
        for (int j = 0; j < Nn; j++){
            float dj = V[j*PADA + j];
            rank += (dj < dv) || (dj == dv && j < l);
        }
        if (rank < KE) ORD[rank] = l;
    }
    __syncwarp();
    // sign convention: column sum of M = row sum of MT (contiguous)
    if (l < KE){
        int i = ORD[l];
        float sum = 0.0f;
        #pragma unroll
        for (int n = 0; n < Nn; n++) sum += MT[i*PADA + n];
        SGN[l] = (sum > 0.0f) ? 1.0f : ((sum < 0.0f) ? -1.0f : 1.0f);
    }
    __syncwarp();
    {
        float* gp = g_pe + (size_t)g*Nn*KE;
        for (int t0 = l; t0 < Nn*KE; t0 += 32){
            int n = t0 / KE, m = t0 % KE;
            float v = MT[ORD[m]*PADA + n] * SGN[m];
            if (isnan(v)) v = 0.0f;
            else if (isinf(v)) v = (v > 0.0f) ? 1.0f : -1.0f;
            gp[t0] = v;
        }
    }
}

// ---------------------------------------------------------------------------
// Kernel B: CTA-per-graph fused SSGConv0 -> LN0 -> SSGConv1 + res -> LN1.
// (R13 version, measured 461-464us three times; unchanged.)
// ---------------------------------------------------------------------------
__global__ void __launch_bounds__(128, 5) dense_kernel(
    const float* __restrict__ features,
    const float* __restrict__ W0, const float* __restrict__ b0,
    const float* __restrict__ W1, const float* __restrict__ b1,
    const float* __restrict__ ln0g, const float* __restrict__ ln0b,
    const float* __restrict__ ln1g, const float* __restrict__ ln1b,
    float* __restrict__ out)
{
    __shared__ __align__(16) float Gt[20*PADG];   // 20 rows (row 19 zeroed)
    __shared__ __align__(16) float XC[20*80];     // x|pe; reused as h1 (20xZPAD)
    __shared__ __align__(16) float Z0[20*ZPAD];
    __shared__ __align__(16) float Z1[20*ZPAD];
    __shared__ __align__(16) float SW[64*PADW];   // staged weights (W0, then W1)
    __shared__ float MU[20], RS[20];

    const int g = blockIdx.x;
    const int b = g >> 10;
    const int t = g & 1023;
    const int tid = threadIdx.x;

    // load G^T (zero pad col and dummy row 19)
    {
        const float* gG = g_G + (size_t)g*Nn*Nn;
        for (int e = tid; e < Nn*Nn; e += 128)
            Gt[(e/Nn)*PADG + (e%Nn)] = gG[e];
        if (tid < 20) Gt[tid*PADG + Nn] = 0.0f;
        if (tid < PADG) Gt[Nn*PADG + tid] = 0.0f;
    }
    // stage W0 (64x80) coalesced into SW rows of stride 84
    for (int i = tid; i < 64*80; i += 128){
        int r = i / 80, c = i - r*80;
        SW[r*PADW + c] = W0[i];
    }
    // load x: XC[n][0:64] = features[b, n, t, :]
    for (int i = tid; i < Nn*64; i += 128){
        int n = i >> 6, dd = i & 63;
        XC[n*80 + dd] = features[((size_t)((b*Nn + n)*Tt + t))*64 + dd];
    }
    // load pe: XC[n][64:80]
    {
        const float* gp = g_pe + (size_t)g*Nn*KE;
        for (int i = tid; i < Nn*KE; i += 128){
            int n = i / KE, m = i % KE;
            XC[n*80 + 64 + m] = gp[i];
        }
    }
    __syncthreads();

    const int d    = tid & 63;
    const int half = tid >> 6;
    const int nb   = half*10;     // nodes nb..nb+9 (row 19 is scratch)

    // ---- GEMM0: Z0 = XC @ W0^T  (2 passes of 40 cols; wreg from smem) ----
    {
        float acc[10];
        #pragma unroll
        for (int m = 0; m < 10; m++) acc[m] = 0.0f;
        #pragma unroll 1
        for (int pass = 0; pass < 2; ++pass){
            float wreg[40];
            #pragma unroll
            for (int j4 = 0; j4 < 10; j4++){
                float4 v = *reinterpret_cast<const float4*>(SW + d*PADW + pass*40 + j4*4);
                wreg[j4*4+0] = v.x; wreg[j4*4+1] = v.y;
                wreg[j4*4+2] = v.z; wreg[j4*4+3] = v.w;
            }
            #pragma unroll
            for (int m = 0; m < 10; m++){
                const float4* xr = reinterpret_cast<const float4*>(XC + (nb+m)*80 + pass*40);
                float a = 0.0f;
                #pragma unroll
                for (int f4 = 0; f4 < 10; f4++){
                    float4 x = xr[f4];
                    a += x.x*wreg[f4*4+0] + x.y*wreg[f4*4+1]
                       + x.z*wreg[f4*4+2] + x.w*wreg[f4*4+3];
                }
                acc[m] += a;
            }
        }
        #pragma unroll
        for (int m = 0; m < 10; m++) Z0[(nb+m)*ZPAD + d] = acc[m];
    }
    __syncthreads();

    // stage W1 (64x64) into SW (overwrites W0; consumers re-read after LN0 sync)
    for (int i = tid; i < 64*64; i += 128){
        int r = i >> 6, c = i & 63;
        SW[r*PADW + c] = W1[i];
    }

    // ---- prop0: Z1 = G^T Z0 + b0 ----
    {
        float zc[20];
        #pragma unroll
        for (int i = 0; i < Nn; i++) zc[i] = Z0[i*ZPAD + d];
        zc[19] = 0.0f;
        float bb = b0[d];
        #pragma unroll
        for (int m = 0; m < 10; m++){
            int n = nb + m;
            const float4* gr = reinterpret_cast<const float4*>(Gt + n*PADG);
            float4 g0 = gr[0], g1 = gr[1], g2 = gr[2], g3 = gr[3], g4 = gr[4];
            float acc =
                g0.x*zc[0]  + g0.y*zc[1]  + g0.z*zc[2]  + g0.w*zc[3]
              + g1.x*zc[4]  + g1.y*zc[5]  + g1.z*zc[6]  + g1.w*zc[7]
              + g2.x*zc[8]  + g2.y*zc[9]  + g2.z*zc[10] + g2.w*zc[11]
              + g3.x*zc[12] + g3.y*zc[13] + g3.z*zc[14] + g3.w*zc[15]
              + g4.x*zc[16] + g4.y*zc[17] + g4.z*zc[18] + g4.w*zc[19];
            Z1[n*ZPAD + d] = acc + bb;
        }
    }
    __syncthreads();

    // ---- LN0 stats on Z1 (stride-68 -> 3-way conflicts max) ----
    if (tid < Nn){
        float mu = 0.0f;
        #pragma unroll
        for (int j = 0; j < 64; j++) mu += Z1[tid*ZPAD + j];
        mu *= (1.0f/64.0f);
        float var = 0.0f;
        #pragma unroll
        for (int j = 0; j < 64; j++){ float dv = Z1[tid*ZPAD + j] - mu; var += dv*dv; }
        var *= (1.0f/64.0f);
        MU[tid] = mu; RS[tid] = rsqrtf(var + LN_EPS);
    }
    if (tid == Nn){ MU[19] = 0.0f; RS[19] = 0.0f; }  // keep scratch row finite
    __syncthreads();
    // LN0 apply -> Z0 (GEMM1 input AND residual)
    {
        float gg = ln0g[d], bbb = ln0b[d];
        #pragma unroll
        for (int m = 0; m < 10; m++){
            int n = nb + m;
            Z0[n*ZPAD + d] = (Z1[n*ZPAD + d] - MU[n])*RS[n]*gg + bbb;
        }
    }
    __syncthreads();

    // ---- GEMM1: Z1 = Z0 @ W1^T  (2 passes of 32 cols) ----
    {
        float acc[10];
        #pragma unroll
        for (int m = 0; m < 10; m++) acc[m] = 0.0f;
        #pragma unroll 1
        for (int pass = 0; pass < 2; ++pass){
            float wreg[32];
            #pragma unroll
            for (int j4 = 0; j4 < 8; j4++){
                float4 v = *reinterpret_cast<const float4*>(SW + d*PADW + pass*32 + j4*4);
                wreg[j4*4+0] = v.x; wreg[j4*4+1] = v.y;
                wreg[j4*4+2] = v.z; wreg[j4*4+3] = v.w;
            }
            #pragma unroll
            for (int m = 0; m < 10; m++){
                const float4* xr = reinterpret_cast<const float4*>(Z0 + (nb+m)*ZPAD + pass*32);
                float a = 0.0f;
                #pragma unroll
                for (int f4 = 0; f4 < 8; f4++){
                    float4 x = xr[f4];
                    a += x.x*wreg[f4*4+0] + x.y*wreg[f4*4+1]
                       + x.z*wreg[f4*4+2] + x.w*wreg[f4*4+3];
                }
                acc[m] += a;
            }
        }
        #pragma unroll
        for (int m = 0; m < 10; m++) Z1[(nb+m)*ZPAD + d] = acc[m];
    }
    __syncthreads();

    // ---- prop1 + residual: h1 = G^T Z1 + b1 + Z0  -> XC (stride ZPAD) ----
    {
        float zc[20];
        #pragma unroll
        for (int i = 0; i < Nn; i++) zc[i] = Z1[i*ZPAD + d];
        zc[19] = 0.0f;
        float bb = b1[d];
        #pragma unroll
        for (int m = 0; m < 10; m++){
            int n = nb + m;
            const float4* gr = reinterpret_cast<const float4*>(Gt + n*PADG);
            float4 g0 = gr[0], g1 = gr[1], g2 = gr[2], g3 = gr[3], g4 = gr[4];
            float acc =
                g0.x*zc[0]  + g0.y*zc[1]  + g0.z*zc[2]  + g0.w*zc[3]
              + g1.x*zc[4]  + g1.y*zc[5]  + g1.z*zc[6]  + g1.w*zc[7]
              + g2.x*zc[8]  + g2.y*zc[9]  + g2.z*zc[10] + g2.w*zc[11]
              + g3.x*zc[12] + g3.y*zc[13] + g3.z*zc[14] + g3.w*zc[15]
              + g4.x*zc[16] + g4.y*zc[17] + g4.z*zc[18] + g4.w*zc[19];
            XC[n*ZPAD + d] = acc + bb + Z0[n*ZPAD + d];
        }
    }
    __syncthreads();

    // ---- LN1 stats on XC ----
    if (tid < Nn){
        float mu = 0.0f;
        #pragma unroll
        for (int j = 0; j < 64; j++) mu += XC[tid*ZPAD + j];
        mu *= (1.0f/64.0f);
        float var = 0.0f;
        #pragma unroll
        for (int j = 0; j < 64; j++){ float dv = XC[tid*ZPAD + j] - mu; var += dv*dv; }
        var *= (1.0f/64.0f);
        MU[tid] = mu; RS[tid] = rsqrtf(var + LN_EPS);
    }
    __syncthreads();
    {
        float gg = ln1g[d], bbb = ln1b[d];
        #pragma unroll
        for (int m = 0; m < 10; m++){
            int n = nb + m;
            if (n < Nn){
                float v = (XC[n*ZPAD + d] - MU[n])*RS[n]*gg + bbb;
                out[((size_t)((b*Nn + n)*Tt + t))*64 + d] = v;
            }
        }
    }
}

// ---------------------------------------------------------------------------
extern "C" void kernel_launch(void* const* d_in, const int* in_sizes, int n_in,
                              void* d_out, int out_size)
{
    const float* features  = (const float*)d_in[0];
    const float* adjacency = (const float*)d_in[1];
    const float* edge_w    = (const float*)d_in[2];
    const float* edge_b    = (const float*)d_in[3];
    const float* gnn0_W    = (const float*)d_in[4];
    const float* gnn0_b    = (const float*)d_in[5];
    const float* gnn1_W    = (const float*)d_in[6];
    const float* gnn1_b    = (const float*)d_in[7];
    const float* ln0_g     = (const float*)d_in[8];
    const float* ln0_b     = (const float*)d_in[9];
    const float* ln1_g     = (const float*)d_in[10];
    const float* ln1_b     = (const float*)d_in[11];
    float* out = (float*)d_out;

    eig_kernel<<<Gg/8, 256>>>(adjacency, edge_w, edge_b);
    dense_kernel<<<Gg, 128>>>(features, gnn0_W, gnn0_b, gnn1_W, gnn1_b,
                              ln0_g, ln0_b, ln1_g, ln1_b, out);
}